// round 15
// baseline (speedup 1.0000x reference)
#include <cuda_runtime.h>
#include <cuda_bf16.h>
#include <cstdint>

#define MAXN 50000
#define MAXN_PAD 50176
#define DD 128
#define MAXE 800000
#define LL 4
#define SCAN_B 1024

// Scratch (no allocations allowed)
__device__ int      g_deg[MAXN];
__device__ int      g_fill[MAXN];
__device__ int      g_rowptr[MAXN + 1];
__device__ int      g_bsum[64];
__device__ int      g_boff[64];
__device__ int      g_csr_src[MAXE];
__device__ float    g_dinv[MAXN];
__device__ float    g_h[(size_t)MAXN * DD];          // h' = (X@W)*dinv[row]
__device__ uint32_t g_xhi[(size_t)MAXN_PAD * 64];    // X planes: bf16x2 words
__device__ uint32_t g_xlo[(size_t)MAXN_PAD * 64];
__device__ unsigned g_barc = 0;
__device__ unsigned g_barg = 0;

// ---------------- preprocessing ----------------

__global__ void zero_counters_kernel(int n) {
    int i = blockIdx.x * blockDim.x + threadIdx.x;
    if (i < n) { g_deg[i] = 0; g_fill[i] = 0; }
}

__global__ void count_deg_kernel(const int* __restrict__ col, int e) {
    int i = blockIdx.x * blockDim.x + threadIdx.x;
    if (i < e) atomicAdd(&g_deg[col[i]], 1);
}

__device__ __forceinline__ int block_excl_scan(int val, int* total) {
    __shared__ int wsum[32];
    int lane = threadIdx.x & 31, wid = threadIdx.x >> 5;
    int v = val;
#pragma unroll
    for (int o = 1; o < 32; o <<= 1) {
        int t = __shfl_up_sync(0xffffffffu, v, o);
        if (lane >= o) v += t;
    }
    if (lane == 31) wsum[wid] = v;
    __syncthreads();
    if (wid == 0) {
        int w = (lane < (blockDim.x >> 5)) ? wsum[lane] : 0;
#pragma unroll
        for (int o = 1; o < 32; o <<= 1) {
            int t = __shfl_up_sync(0xffffffffu, w, o);
            if (lane >= o) w += t;
        }
        wsum[lane] = w;
    }
    __syncthreads();
    int excl = v - val + (wid > 0 ? wsum[wid - 1] : 0);
    *total = wsum[(blockDim.x >> 5) - 1];
    return excl;
}

__global__ void scan1_kernel(int n) {
    int i = blockIdx.x * SCAN_B + threadIdx.x;
    int v = (i < n) ? g_deg[i] : 0;
    if (i < n) g_dinv[i] = rsqrtf((float)(v + 1));  // +1 self-loop
    int total;
    int excl = block_excl_scan(v, &total);
    if (i <= n) g_rowptr[i] = excl;
    if (threadIdx.x == 0) g_bsum[blockIdx.x] = total;
}

__global__ void scan2_kernel(int nb) {
    int v = (threadIdx.x < nb) ? g_bsum[threadIdx.x] : 0;
    int total;
    int excl = block_excl_scan(v, &total);
    if (threadIdx.x < nb) g_boff[threadIdx.x] = excl;
    if (threadIdx.x == 0) g_boff[nb] = total;
}

__global__ void scan3_kernel(int n, int nb) {
    int i = blockIdx.x * SCAN_B + threadIdx.x;
    if (i < n) g_rowptr[i] += g_boff[blockIdx.x];
    if (i == 0) g_rowptr[n] = g_boff[nb];
}

__global__ void fill_csr_kernel(const int* __restrict__ row,
                                const int* __restrict__ col, int e) {
    int i = blockIdx.x * blockDim.x + threadIdx.x;
    if (i < e) {
        int c = col[i];
        int p = g_rowptr[c] + atomicAdd(&g_fill[c], 1);
        g_csr_src[p] = row[i];
    }
}

// ---------------- fused GCN: 4 x (GEMM -> grid barrier -> aggregate) ----------------

#define PSTR 68
#define PLANE (128 * PSTR)                      // 8704 words
#define GEMM_SMEM (6 * PLANE * 4)               // 208896 B

// generation grid barrier (grid == resident blocks: 1 CTA/SM by smem)
__device__ __forceinline__ void grid_bar() {
    __threadfence();
    __syncthreads();
    if (threadIdx.x == 0) {
        unsigned gen = atomicAdd(&g_barg, 0u);
        if (atomicAdd(&g_barc, 1u) == gridDim.x - 1) {
            atomicExch(&g_barc, 0u);
            __threadfence();
            atomicAdd(&g_barg, 1u);
        } else {
            while (atomicAdd(&g_barg, 0u) == gen) {}
        }
    }
    __syncthreads();
}

__device__ __forceinline__ void mma_bf16(float* c, const uint32_t* a,
                                         uint32_t b0, uint32_t b1) {
    asm volatile(
        "mma.sync.aligned.m16n8k16.row.col.f32.bf16.bf16.f32 "
        "{%0,%1,%2,%3}, {%4,%5,%6,%7}, {%8,%9}, {%0,%1,%2,%3};"
        : "+f"(c[0]), "+f"(c[1]), "+f"(c[2]), "+f"(c[3])
        : "r"(a[0]), "r"(a[1]), "r"(a[2]), "r"(a[3]), "r"(b0), "r"(b1));
}

__device__ __forceinline__ void ldsm4(uint32_t* r, uint32_t addr) {
    asm volatile(
        "ldmatrix.sync.aligned.m8n8.x4.shared.b16 {%0,%1,%2,%3}, [%4];"
        : "=r"(r[0]), "=r"(r[1]), "=r"(r[2]), "=r"(r[3]) : "r"(addr));
}

__device__ __forceinline__ uint32_t pack2(float x, float y) {
    __nv_bfloat162 h = make_bfloat162(__float2bfloat16(x), __float2bfloat16(y));
    return *(uint32_t*)&h;
}

__device__ __forceinline__ void cvt_store_a(uint32_t* hi, uint32_t* lo,
                                            float4 v, int r, int c4) {
    float hx = __bfloat162float(__float2bfloat16(v.x));
    float hy = __bfloat162float(__float2bfloat16(v.y));
    float hz = __bfloat162float(__float2bfloat16(v.z));
    float hw = __bfloat162float(__float2bfloat16(v.w));
    int p = r * PSTR + 2 * c4;
    *(uint2*)&hi[p] = make_uint2(pack2(v.x, v.y), pack2(v.z, v.w));
    *(uint2*)&lo[p] = make_uint2(pack2(v.x - hx, v.y - hy),
                                 pack2(v.z - hz, v.w - hw));
}

__device__ __forceinline__ void stage_w(const float* __restrict__ W,
                                        uint32_t* sBhi, uint32_t* sBlo,
                                        int tid) {
    for (int i = tid; i < 64 * 128; i += 1024) {
        int kw = i >> 7, nn = i & 127;
        float v0 = W[(size_t)(2 * kw) * DD + nn];
        float v1 = W[(size_t)(2 * kw + 1) * DD + nn];
        float h0 = __bfloat162float(__float2bfloat16(v0));
        float h1 = __bfloat162float(__float2bfloat16(v1));
        int p = nn * PSTR + kw;
        sBhi[p] = pack2(v0, v1);
        sBlo[p] = pack2(v0 - h0, v1 - h1);
    }
}

__device__ __forceinline__ void stage_a_async(uint32_t dstHi, int rowBase,
                                              int tid) {
#pragma unroll
    for (int j = 0; j < 2; ++j) {
        int c = tid + j * 1024;
        int row = c >> 4, col = c & 15;
        uint32_t so = dstHi + (uint32_t)(row * PSTR * 4 + col * 16);
        const uint32_t* gp = g_xhi + ((size_t)(rowBase + row) * 64 + col * 4);
        asm volatile("cp.async.cg.shared.global [%0], [%1], 16;"
                     :: "r"(so), "l"(gp));
    }
#pragma unroll
    for (int j = 0; j < 2; ++j) {
        int c = tid + j * 1024;
        int row = c >> 4, col = c & 15;
        uint32_t so = dstHi + PLANE * 4 + (uint32_t)(row * PSTR * 4 + col * 16);
        const uint32_t* gp = g_xlo + ((size_t)(rowBase + row) * 64 + col * 4);
        asm volatile("cp.async.cg.shared.global [%0], [%1], 16;"
                     :: "r"(so), "l"(gp));
    }
    asm volatile("cp.async.commit_group;" ::: "memory");
}

__device__ __forceinline__ void gemm_tile_body(
    uint32_t aHiA, uint32_t aLoA, uint32_t sBhiA, uint32_t sBloA,
    uint32_t bOff0, uint32_t bOff1, int t, int wm, int wn, int g, int q,
    int n) {
    float c[4][4];
#pragma unroll
    for (int nt = 0; nt < 4; ++nt)
#pragma unroll
        for (int j = 0; j < 4; ++j) c[nt][j] = 0.f;

#pragma unroll
    for (int ks = 0; ks < 8; ++ks) {
        uint32_t kb = (uint32_t)(ks * 32);

        uint32_t ahi[4], alo[4];
        ldsm4(ahi, aHiA + kb);
        ldsm4(alo, aLoA + kb);

        uint32_t bh[8], bl[8];
        ldsm4(bh + 0, sBhiA + bOff0 + kb);
        ldsm4(bh + 4, sBhiA + bOff1 + kb);
        ldsm4(bl + 0, sBloA + bOff0 + kb);
        ldsm4(bl + 4, sBloA + bOff1 + kb);

#pragma unroll
        for (int nt = 0; nt < 4; ++nt)
            mma_bf16(c[nt], ahi, bh[2 * nt], bh[2 * nt + 1]);
#pragma unroll
        for (int nt = 0; nt < 4; ++nt)
            mma_bf16(c[nt], ahi, bl[2 * nt], bl[2 * nt + 1]);
#pragma unroll
        for (int nt = 0; nt < 4; ++nt)
            mma_bf16(c[nt], alo, bh[2 * nt], bh[2 * nt + 1]);
    }

    int m0 = wm * 16 + g;
    int r0 = t * 128 + m0;
    int r1 = r0 + 8;
    float d0 = (r0 < n) ? g_dinv[r0] : 0.f;
    float d1 = (r1 < n) ? g_dinv[r1] : 0.f;
#pragma unroll
    for (int nt = 0; nt < 4; ++nt) {
        int col = wn * 32 + nt * 8 + 2 * q;
        if (r0 < n)
            *(float2*)(g_h + (size_t)r0 * DD + col) =
                make_float2(c[nt][0] * d0, c[nt][1] * d0);
        if (r1 < n)
            *(float2*)(g_h + (size_t)r1 * DD + col) =
                make_float2(c[nt][2] * d1, c[nt][3] * d1);
    }
}

__global__ __launch_bounds__(1024, 1)
void gcn_fused(const float* __restrict__ X, const float* __restrict__ W,
               const float* __restrict__ bias, float* __restrict__ out,
               int n, int numTiles) {
    extern __shared__ uint32_t smem[];
    uint32_t* sBhi = smem + 4 * PLANE;
    uint32_t* sBlo = sBhi + PLANE;

    int tid  = threadIdx.x;
    int lane = tid & 31;
    int w    = tid >> 5;
    int wm   = w & 7;
    int wn   = w >> 3;
    int g    = lane >> 2;
    int q    = lane & 3;

    uint32_t aOff = ((uint32_t)(wm * 16 + (lane & 15)) * PSTR +
                     (uint32_t)((lane >> 4) * 4)) * 4u;
    uint32_t bRow0 = (uint32_t)(wn * 32 + (lane & 7) + ((lane >> 4) & 1) * 8);
    uint32_t bKch  = (uint32_t)(((lane >> 3) & 1) * 4);
    uint32_t bOff0 = (bRow0 * PSTR + bKch) * 4u;
    uint32_t bOff1 = ((bRow0 + 16) * PSTR + bKch) * 4u;

    uint32_t smemA = (uint32_t)__cvta_generic_to_shared(smem);
    uint32_t sBhiA = (uint32_t)__cvta_generic_to_shared(sBhi);
    uint32_t sBloA = (uint32_t)__cvta_generic_to_shared(sBlo);

    // W for layer 0
    stage_w(W, sBhi, sBlo, tid);

    for (int l = 0; l < LL; ++l) {
        // ================= GEMM phase =================
        int cur = 0;
        if (l == 0) {
            // fp32 X path: stage tile 0 via LDG+CVT+STS
            int rowBase = blockIdx.x * 128;
            for (int i = tid; i < 128 * 32; i += 1024) {
                int r = i >> 5, c4 = i & 31;
                float4 v = make_float4(0.f, 0.f, 0.f, 0.f);
                if (rowBase + r < n)
                    v = __ldg(&((const float4*)X)[(size_t)(rowBase + r) * 32 + c4]);
                cvt_store_a(smem, smem + PLANE, v, r, c4);
            }
            __syncthreads();

            for (int t = blockIdx.x; t < numTiles; t += gridDim.x) {
                int tn = t + gridDim.x;
                bool hasNext = tn < numTiles;
                float4 pv[4];
                if (hasNext) {
#pragma unroll
                    for (int j = 0; j < 4; ++j) {
                        int idx = tid + j * 1024;
                        int row = tn * 128 + (idx >> 5);
                        pv[j] = (row < n)
                                    ? __ldg(&((const float4*)X)[(size_t)row * 32 +
                                                                (idx & 31)])
                                    : make_float4(0.f, 0.f, 0.f, 0.f);
                    }
                }
                uint32_t aHiA = smemA + (cur ? 2 * PLANE * 4 : 0) + aOff;
                gemm_tile_body(aHiA, aHiA + PLANE * 4, sBhiA, sBloA,
                               bOff0, bOff1, t, wm, wn, g, q, n);
                if (hasNext) {
                    uint32_t* Nhi = smem + (cur ? 0 : 2 * PLANE);
                    uint32_t* Nlo = Nhi + PLANE;
#pragma unroll
                    for (int j = 0; j < 4; ++j) {
                        int idx = tid + j * 1024;
                        cvt_store_a(Nhi, Nlo, pv[j], idx >> 5, idx & 31);
                    }
                }
                __syncthreads();
                cur ^= 1;
            }
        } else {
            // pre-split plane path via cp.async
            stage_a_async(smemA, blockIdx.x * 128, tid);
            asm volatile("cp.async.wait_group 0;" ::: "memory");
            __syncthreads();

            for (int t = blockIdx.x; t < numTiles; t += gridDim.x) {
                int tn = t + gridDim.x;
                bool hasNext = tn < numTiles;
                if (hasNext)
                    stage_a_async(smemA + (cur ? 0 : 2 * PLANE * 4),
                                  tn * 128, tid);
                uint32_t aHiA = smemA + (cur ? 2 * PLANE * 4 : 0) + aOff;
                gemm_tile_body(aHiA, aHiA + PLANE * 4, sBhiA, sBloA,
                               bOff0, bOff1, t, wm, wn, g, q, n);
                if (hasNext)
                    asm volatile("cp.async.wait_group 0;" ::: "memory");
                __syncthreads();
                cur ^= 1;
            }
        }
        grid_bar();  // all of g_h visible to all SMs

        // stage W for the NEXT layer while aggregating (smem idle otherwise)
        if (l + 1 < LL)
            stage_w(W + (size_t)(l + 1) * DD * DD, sBhi, sBlo, tid);

        // ================= aggregate phase =================
        // No per-launch L1 flush inside a persistent kernel: g_h reads must
        // bypass L1 (__ldcg) — other SMs wrote it since our last read.
        const float* bl = bias + (size_t)l * DD;
        int writePlanes = (l < LL - 1);
        for (int node = blockIdx.x * 32 + w; node < n; node += gridDim.x * 32) {
            const float4* H = (const float4*)g_h;
            float4 acc = __ldcg(&H[(size_t)node * 32 + lane]);  // self-loop

            int p   = g_rowptr[node];
            int end = g_rowptr[node + 1];
            for (; p + 4 <= end; p += 4) {
                int s0 = __ldg(&g_csr_src[p + 0]);
                int s1 = __ldg(&g_csr_src[p + 1]);
                int s2 = __ldg(&g_csr_src[p + 2]);
                int s3 = __ldg(&g_csr_src[p + 3]);
                float4 v0 = __ldcg(&H[(size_t)s0 * 32 + lane]);
                float4 v1 = __ldcg(&H[(size_t)s1 * 32 + lane]);
                float4 v2 = __ldcg(&H[(size_t)s2 * 32 + lane]);
                float4 v3 = __ldcg(&H[(size_t)s3 * 32 + lane]);
                acc.x += (v0.x + v1.x) + (v2.x + v3.x);
                acc.y += (v0.y + v1.y) + (v2.y + v3.y);
                acc.z += (v0.z + v1.z) + (v2.z + v3.z);
                acc.w += (v0.w + v1.w) + (v2.w + v3.w);
            }
            for (; p < end; ++p) {
                int s = __ldg(&g_csr_src[p]);
                float4 v = __ldcg(&H[(size_t)s * 32 + lane]);
                acc.x += v.x; acc.y += v.y; acc.z += v.z; acc.w += v.w;
            }

            float di  = g_dinv[node];
            float4 bb = __ldg(&((const float4*)bl)[lane]);
            float4 o;
            o.x = fmaxf(acc.x * di + bb.x, 0.f);
            o.y = fmaxf(acc.y * di + bb.y, 0.f);
            o.z = fmaxf(acc.z * di + bb.z, 0.f);
            o.w = fmaxf(acc.w * di + bb.w, 0.f);

            if (writePlanes) {
                float hx = __bfloat162float(__float2bfloat16(o.x));
                float hy = __bfloat162float(__float2bfloat16(o.y));
                float hz = __bfloat162float(__float2bfloat16(o.z));
                float hw = __bfloat162float(__float2bfloat16(o.w));
                size_t base = (size_t)node * 64 + 2 * lane;
                g_xhi[base]     = pack2(o.x, o.y);
                g_xhi[base + 1] = pack2(o.z, o.w);
                g_xlo[base]     = pack2(o.x - hx, o.y - hy);
                g_xlo[base + 1] = pack2(o.z - hz, o.w - hw);
            } else {
                ((float4*)out)[(size_t)node * 32 + lane] = o;
            }
        }
        grid_bar();  // planes visible before next layer's cp.async reads
    }
}

extern "C" void kernel_launch(void* const* d_in, const int* in_sizes, int n_in,
                              void* d_out, int out_size) {
    const float* x  = (const float*)d_in[0];
    const int*   ei = (const int*)d_in[1];
    const float* W  = (const float*)d_in[4];
    const float* b  = (const float*)d_in[5];
    float* out = (float*)d_out;

    int n = in_sizes[0] / DD;      // 50000
    int e = in_sizes[1] / 2;       // 800000
    const int* rowp = ei;          // sources
    const int* colp = ei + e;      // destinations
    int nb = (n + SCAN_B - 1) / SCAN_B;
    int numTiles = (n + 127) / 128;

    int sms = 148;
    cudaDeviceGetAttribute(&sms, cudaDevAttrMultiProcessorCount, 0);

    cudaFuncSetAttribute(gcn_fused,
                         cudaFuncAttributeMaxDynamicSharedMemorySize, GEMM_SMEM);

    zero_counters_kernel<<<(n + 255) / 256, 256>>>(n);
    count_deg_kernel<<<(e + 255) / 256, 256>>>(colp, e);
    scan1_kernel<<<nb, SCAN_B>>>(n);
    scan2_kernel<<<1, SCAN_B>>>(nb);
    scan3_kernel<<<nb, SCAN_B>>>(n, nb);
    fill_csr_kernel<<<(e + 255) / 256, 256>>>(rowp, colp, e);
    gcn_fused<<<sms, 1024, GEMM_SMEM>>>(x, W, b, out, n, numTiles);
}

// round 16
// speedup vs baseline: 1.1535x; 1.1535x over previous
#include <cuda_runtime.h>
#include <cuda_bf16.h>
#include <cstdint>

#define MAXN 50000
#define MAXN_PAD 50176
#define DD 128
#define MAXE 800000
#define LL 4
#define SCAN_B 1024

// Scratch (no allocations allowed)
__device__ int      g_deg[MAXN];
__device__ int      g_fill[MAXN];
__device__ int      g_rowptr[MAXN + 1];
__device__ int      g_bsum[64];
__device__ int      g_boff[64];
__device__ int      g_csr_src[MAXE];
__device__ float    g_dinv[MAXN];
__device__ float    g_h[(size_t)MAXN * DD];          // h' = (X@W)*dinv[row]
__device__ uint32_t g_xhi[(size_t)MAXN_PAD * 64];    // X planes: bf16x2 words
__device__ uint32_t g_xlo[(size_t)MAXN_PAD * 64];

// ---------------- preprocessing ----------------

__global__ void zero_counters_kernel(int n) {
    int i = blockIdx.x * blockDim.x + threadIdx.x;
    if (i < n) { g_deg[i] = 0; g_fill[i] = 0; }
}

__global__ void count_deg_kernel(const int* __restrict__ col, int e) {
    int i = blockIdx.x * blockDim.x + threadIdx.x;
    if (i < e) atomicAdd(&g_deg[col[i]], 1);
}

__global__ void dinv_kernel(int n) {
    int i = blockIdx.x * blockDim.x + threadIdx.x;
    if (i < n) g_dinv[i] = rsqrtf((float)(g_deg[i] + 1));  // +1 self-loop
}

__device__ __forceinline__ int block_excl_scan(int val, int* total) {
    __shared__ int wsum[32];
    int lane = threadIdx.x & 31, wid = threadIdx.x >> 5;
    int v = val;
#pragma unroll
    for (int o = 1; o < 32; o <<= 1) {
        int t = __shfl_up_sync(0xffffffffu, v, o);
        if (lane >= o) v += t;
    }
    if (lane == 31) wsum[wid] = v;
    __syncthreads();
    if (wid == 0) {
        int w = (lane < (blockDim.x >> 5)) ? wsum[lane] : 0;
#pragma unroll
        for (int o = 1; o < 32; o <<= 1) {
            int t = __shfl_up_sync(0xffffffffu, w, o);
            if (lane >= o) w += t;
        }
        wsum[lane] = w;
    }
    __syncthreads();
    int excl = v - val + (wid > 0 ? wsum[wid - 1] : 0);
    *total = wsum[(blockDim.x >> 5) - 1];
    return excl;
}

__global__ void scan1_kernel(int n) {
    int i = blockIdx.x * SCAN_B + threadIdx.x;
    int v = (i < n) ? g_deg[i] : 0;
    int total;
    int excl = block_excl_scan(v, &total);
    if (i <= n) g_rowptr[i] = excl;
    if (threadIdx.x == 0) g_bsum[blockIdx.x] = total;
}

__global__ void scan2_kernel(int nb) {
    int v = (threadIdx.x < nb) ? g_bsum[threadIdx.x] : 0;
    int total;
    int excl = block_excl_scan(v, &total);
    if (threadIdx.x < nb) g_boff[threadIdx.x] = excl;
    if (threadIdx.x == 0) g_boff[nb] = total;
}

__global__ void scan3_kernel(int n, int nb) {
    int i = blockIdx.x * SCAN_B + threadIdx.x;
    if (i < n) g_rowptr[i] += g_boff[blockIdx.x];
    if (i == 0) g_rowptr[n] = g_boff[nb];
}

__global__ void fill_csr_kernel(const int* __restrict__ row,
                                const int* __restrict__ col, int e) {
    int i = blockIdx.x * blockDim.x + threadIdx.x;
    if (i < e) {
        int c = col[i];
        int p = g_rowptr[c] + atomicAdd(&g_fill[c], 1);
        g_csr_src[p] = row[i];
    }
}

// ---------------- shared GEMM pieces ----------------

#define PSTR 68
#define PLANE (128 * PSTR)                      // 8704 words
#define GEMM_SMEM (6 * PLANE * 4)               // 208896 B

__device__ __forceinline__ void mma_bf16(float* c, const uint32_t* a,
                                         uint32_t b0, uint32_t b1) {
    asm volatile(
        "mma.sync.aligned.m16n8k16.row.col.f32.bf16.bf16.f32 "
        "{%0,%1,%2,%3}, {%4,%5,%6,%7}, {%8,%9}, {%0,%1,%2,%3};"
        : "+f"(c[0]), "+f"(c[1]), "+f"(c[2]), "+f"(c[3])
        : "r"(a[0]), "r"(a[1]), "r"(a[2]), "r"(a[3]), "r"(b0), "r"(b1));
}

__device__ __forceinline__ void ldsm4(uint32_t* r, uint32_t addr) {
    asm volatile(
        "ldmatrix.sync.aligned.m8n8.x4.shared.b16 {%0,%1,%2,%3}, [%4];"
        : "=r"(r[0]), "=r"(r[1]), "=r"(r[2]), "=r"(r[3]) : "r"(addr));
}

__device__ __forceinline__ uint32_t pack2(float x, float y) {
    __nv_bfloat162 h = make_bfloat162(__float2bfloat16(x), __float2bfloat16(y));
    return *(uint32_t*)&h;
}

__device__ __forceinline__ void cvt_store_a(uint32_t* hi, uint32_t* lo,
                                            float4 v, int r, int c4) {
    float hx = __bfloat162float(__float2bfloat16(v.x));
    float hy = __bfloat162float(__float2bfloat16(v.y));
    float hz = __bfloat162float(__float2bfloat16(v.z));
    float hw = __bfloat162float(__float2bfloat16(v.w));
    int p = r * PSTR + 2 * c4;
    *(uint2*)&hi[p] = make_uint2(pack2(v.x, v.y), pack2(v.z, v.w));
    *(uint2*)&lo[p] = make_uint2(pack2(v.x - hx, v.y - hy),
                                 pack2(v.z - hz, v.w - hw));
}

// stage W into n-major plane rows [ncol][PSTR]
__device__ __forceinline__ void stage_w(const float* __restrict__ W,
                                        uint32_t* sBhi, uint32_t* sBlo,
                                        int tid) {
    for (int i = tid; i < 64 * 128; i += 1024) {
        int kw = i >> 7, nn = i & 127;
        float v0 = W[(size_t)(2 * kw) * DD + nn];
        float v1 = W[(size_t)(2 * kw + 1) * DD + nn];
        float h0 = __bfloat162float(__float2bfloat16(v0));
        float h1 = __bfloat162float(__float2bfloat16(v1));
        int p = nn * PSTR + kw;
        sBhi[p] = pack2(v0, v1);
        sBlo[p] = pack2(v0 - h0, v1 - h1);
    }
}

// mainloop body: 8 k16-steps of 6 ldmatrix + 12 mma, then epilogue
__device__ __forceinline__ void gemm_tile_body(
    uint32_t aHiA, uint32_t aLoA, uint32_t sBhiA, uint32_t sBloA,
    uint32_t bOff0, uint32_t bOff1, int t, int wm, int wn, int g, int q,
    int n) {
    float c[4][4];
#pragma unroll
    for (int nt = 0; nt < 4; ++nt)
#pragma unroll
        for (int j = 0; j < 4; ++j) c[nt][j] = 0.f;

#pragma unroll
    for (int ks = 0; ks < 8; ++ks) {
        uint32_t kb = (uint32_t)(ks * 32);

        uint32_t ahi[4], alo[4];
        ldsm4(ahi, aHiA + kb);
        ldsm4(alo, aLoA + kb);

        uint32_t bh[8], bl[8];
        ldsm4(bh + 0, sBhiA + bOff0 + kb);
        ldsm4(bh + 4, sBhiA + bOff1 + kb);
        ldsm4(bl + 0, sBloA + bOff0 + kb);
        ldsm4(bl + 4, sBloA + bOff1 + kb);

#pragma unroll
        for (int nt = 0; nt < 4; ++nt)
            mma_bf16(c[nt], ahi, bh[2 * nt], bh[2 * nt + 1]);
#pragma unroll
        for (int nt = 0; nt < 4; ++nt)
            mma_bf16(c[nt], ahi, bl[2 * nt], bl[2 * nt + 1]);
#pragma unroll
        for (int nt = 0; nt < 4; ++nt)
            mma_bf16(c[nt], alo, bh[2 * nt], bh[2 * nt + 1]);
    }

    int m0 = wm * 16 + g;
    int r0 = t * 128 + m0;
    int r1 = r0 + 8;
    float d0 = (r0 < n) ? g_dinv[r0] : 0.f;
    float d1 = (r1 < n) ? g_dinv[r1] : 0.f;
#pragma unroll
    for (int nt = 0; nt < 4; ++nt) {
        int col = wn * 32 + nt * 8 + 2 * q;
        if (r0 < n)
            *(float2*)(g_h + (size_t)r0 * DD + col) =
                make_float2(c[nt][0] * d0, c[nt][1] * d0);
        if (r1 < n)
            *(float2*)(g_h + (size_t)r1 * DD + col) =
                make_float2(c[nt][2] * d1, c[nt][3] * d1);
    }
}

// ---------------- GEMM (layer 0): reads fp32 X, LDG+CVT+STS prefetch ----------------
__global__ __launch_bounds__(1024, 1)
void gemm_f32(const float* __restrict__ X, const float* __restrict__ W,
              int n, int numTiles) {
    extern __shared__ uint32_t smem[];
    uint32_t* sBhi = smem + 4 * PLANE;
    uint32_t* sBlo = sBhi + PLANE;

    int tid  = threadIdx.x;
    int lane = tid & 31;
    int w    = tid >> 5;
    int wm   = w & 7;
    int wn   = w >> 3;
    int g    = lane >> 2;
    int q    = lane & 3;

    stage_w(W, sBhi, sBlo, tid);

    {
        int rowBase = blockIdx.x * 128;
        for (int i = tid; i < 128 * 32; i += 1024) {
            int r = i >> 5, c4 = i & 31;
            float4 v = make_float4(0.f, 0.f, 0.f, 0.f);
            if (rowBase + r < n)
                v = __ldg(&((const float4*)X)[(size_t)(rowBase + r) * 32 + c4]);
            cvt_store_a(smem, smem + PLANE, v, r, c4);
        }
    }
    __syncthreads();

    uint32_t aOff = ((uint32_t)(wm * 16 + (lane & 15)) * PSTR +
                     (uint32_t)((lane >> 4) * 4)) * 4u;
    uint32_t bRow0 = (uint32_t)(wn * 32 + (lane & 7) + ((lane >> 4) & 1) * 8);
    uint32_t bKch  = (uint32_t)(((lane >> 3) & 1) * 4);
    uint32_t bOff0 = (bRow0 * PSTR + bKch) * 4u;
    uint32_t bOff1 = ((bRow0 + 16) * PSTR + bKch) * 4u;

    uint32_t smemA = (uint32_t)__cvta_generic_to_shared(smem);
    uint32_t sBhiA = (uint32_t)__cvta_generic_to_shared(sBhi);
    uint32_t sBloA = (uint32_t)__cvta_generic_to_shared(sBlo);

    int cur = 0;
    for (int t = blockIdx.x; t < numTiles; t += gridDim.x) {
        int tn = t + gridDim.x;
        bool hasNext = tn < numTiles;

        float4 pv[4];
        if (hasNext) {
#pragma unroll
            for (int j = 0; j < 4; ++j) {
                int idx = tid + j * 1024;
                int row = tn * 128 + (idx >> 5);
                pv[j] = (row < n)
                            ? __ldg(&((const float4*)X)[(size_t)row * 32 + (idx & 31)])
                            : make_float4(0.f, 0.f, 0.f, 0.f);
            }
        }

        uint32_t aHiA = smemA + (cur ? 2 * PLANE * 4 : 0) + aOff;
        gemm_tile_body(aHiA, aHiA + PLANE * 4, sBhiA, sBloA, bOff0, bOff1,
                       t, wm, wn, g, q, n);

        if (hasNext) {
            uint32_t* Nhi = smem + (cur ? 0 : 2 * PLANE);
            uint32_t* Nlo = Nhi + PLANE;
#pragma unroll
            for (int j = 0; j < 4; ++j) {
                int idx = tid + j * 1024;
                cvt_store_a(Nhi, Nlo, pv[j], idx >> 5, idx & 31);
            }
        }
        __syncthreads();
        cur ^= 1;
    }
}

// ---------------- GEMM (layers 1-3): reads pre-split planes via cp.async ----------------

__device__ __forceinline__ void stage_a_async(uint32_t dstHi, int rowBase,
                                              int tid) {
#pragma unroll
    for (int j = 0; j < 2; ++j) {
        int c = tid + j * 1024;
        int row = c >> 4, col = c & 15;
        uint32_t so = dstHi + (uint32_t)(row * PSTR * 4 + col * 16);
        const uint32_t* gp = g_xhi + ((size_t)(rowBase + row) * 64 + col * 4);
        asm volatile("cp.async.cg.shared.global [%0], [%1], 16;"
                     :: "r"(so), "l"(gp));
    }
#pragma unroll
    for (int j = 0; j < 2; ++j) {
        int c = tid + j * 1024;
        int row = c >> 4, col = c & 15;
        uint32_t so = dstHi + PLANE * 4 + (uint32_t)(row * PSTR * 4 + col * 16);
        const uint32_t* gp = g_xlo + ((size_t)(rowBase + row) * 64 + col * 4);
        asm volatile("cp.async.cg.shared.global [%0], [%1], 16;"
                     :: "r"(so), "l"(gp));
    }
    asm volatile("cp.async.commit_group;" ::: "memory");
}

__global__ __launch_bounds__(1024, 1)
void gemm_planes(const float* __restrict__ W, int n, int numTiles) {
    extern __shared__ uint32_t smem[];
    uint32_t* sBhi = smem + 4 * PLANE;
    uint32_t* sBlo = sBhi + PLANE;

    int tid  = threadIdx.x;
    int lane = tid & 31;
    int w    = tid >> 5;
    int wm   = w & 7;
    int wn   = w >> 3;
    int g    = lane >> 2;
    int q    = lane & 3;

    uint32_t smemA = (uint32_t)__cvta_generic_to_shared(smem);

    stage_a_async(smemA, blockIdx.x * 128, tid);
    stage_w(W, sBhi, sBlo, tid);
    asm volatile("cp.async.wait_group 0;" ::: "memory");
    __syncthreads();

    uint32_t aOff = ((uint32_t)(wm * 16 + (lane & 15)) * PSTR +
                     (uint32_t)((lane >> 4) * 4)) * 4u;
    uint32_t bRow0 = (uint32_t)(wn * 32 + (lane & 7) + ((lane >> 4) & 1) * 8);
    uint32_t bKch  = (uint32_t)(((lane >> 3) & 1) * 4);
    uint32_t bOff0 = (bRow0 * PSTR + bKch) * 4u;
    uint32_t bOff1 = ((bRow0 + 16) * PSTR + bKch) * 4u;

    uint32_t sBhiA = (uint32_t)__cvta_generic_to_shared(sBhi);
    uint32_t sBloA = (uint32_t)__cvta_generic_to_shared(sBlo);

    int cur = 0;
    for (int t = blockIdx.x; t < numTiles; t += gridDim.x) {
        int tn = t + gridDim.x;
        bool hasNext = tn < numTiles;

        if (hasNext)
            stage_a_async(smemA + (cur ? 0 : 2 * PLANE * 4), tn * 128, tid);

        uint32_t aHiA = smemA + (cur ? 2 * PLANE * 4 : 0) + aOff;
        gemm_tile_body(aHiA, aHiA + PLANE * 4, sBhiA, sBloA, bOff0, bOff1,
                       t, wm, wn, g, q, n);

        if (hasNext)
            asm volatile("cp.async.wait_group 0;" ::: "memory");
        __syncthreads();
        cur ^= 1;
    }
}

// ---------------- Aggregation: gather, no atomics ----------------
__global__ void aggregate_kernel(const float* __restrict__ bias,
                                 float* __restrict__ out, int writePlanes,
                                 int n) {
    int node = (blockIdx.x * blockDim.x + threadIdx.x) >> 5;
    int lane = threadIdx.x & 31;
    if (node >= n) return;

    const float4* H = (const float4*)g_h;
    float4 acc = __ldg(&H[(size_t)node * 32 + lane]);  // self-loop h'

    int p   = g_rowptr[node];
    int end = g_rowptr[node + 1];
    for (; p + 4 <= end; p += 4) {
        int s0 = __ldg(&g_csr_src[p + 0]);
        int s1 = __ldg(&g_csr_src[p + 1]);
        int s2 = __ldg(&g_csr_src[p + 2]);
        int s3 = __ldg(&g_csr_src[p + 3]);
        float4 v0 = __ldg(&H[(size_t)s0 * 32 + lane]);
        float4 v1 = __ldg(&H[(size_t)s1 * 32 + lane]);
        float4 v2 = __ldg(&H[(size_t)s2 * 32 + lane]);
        float4 v3 = __ldg(&H[(size_t)s3 * 32 + lane]);
        acc.x += (v0.x + v1.x) + (v2.x + v3.x);
        acc.y += (v0.y + v1.y) + (v2.y + v3.y);
        acc.z += (v0.z + v1.z) + (v2.z + v3.z);
        acc.w += (v0.w + v1.w) + (v2.w + v3.w);
    }
    for (; p < end; ++p) {
        int s = __ldg(&g_csr_src[p]);
        float4 v = __ldg(&H[(size_t)s * 32 + lane]);
        acc.x += v.x; acc.y += v.y; acc.z += v.z; acc.w += v.w;
    }

    float di  = g_dinv[node];
    float4 bb = __ldg(&((const float4*)bias)[lane]);
    float4 o;
    o.x = fmaxf(acc.x * di + bb.x, 0.f);
    o.y = fmaxf(acc.y * di + bb.y, 0.f);
    o.z = fmaxf(acc.z * di + bb.z, 0.f);
    o.w = fmaxf(acc.w * di + bb.w, 0.f);

    if (writePlanes) {
        float hx = __bfloat162float(__float2bfloat16(o.x));
        float hy = __bfloat162float(__float2bfloat16(o.y));
        float hz = __bfloat162float(__float2bfloat16(o.z));
        float hw = __bfloat162float(__float2bfloat16(o.w));
        size_t base = (size_t)node * 64 + 2 * lane;
        g_xhi[base]     = pack2(o.x, o.y);
        g_xhi[base + 1] = pack2(o.z, o.w);
        g_xlo[base]     = pack2(o.x - hx, o.y - hy);
        g_xlo[base + 1] = pack2(o.z - hz, o.w - hw);
    } else {
        ((float4*)out)[(size_t)node * 32 + lane] = o;
    }
}

extern "C" void kernel_launch(void* const* d_in, const int* in_sizes, int n_in,
                              void* d_out, int out_size) {
    const float* x  = (const float*)d_in[0];
    const int*   ei = (const int*)d_in[1];
    const float* W  = (const float*)d_in[4];
    const float* b  = (const float*)d_in[5];
    float* out = (float*)d_out;

    int n = in_sizes[0] / DD;      // 50000
    int e = in_sizes[1] / 2;       // 800000
    const int* rowp = ei;          // sources
    const int* colp = ei + e;      // destinations
    int nb = (n + SCAN_B - 1) / SCAN_B;
    int numTiles = (n + 127) / 128;

    int sms = 148;
    cudaDeviceGetAttribute(&sms, cudaDevAttrMultiProcessorCount, 0);
    int gemmGrid = numTiles < sms ? numTiles : sms;

    cudaFuncSetAttribute(gemm_f32,
                         cudaFuncAttributeMaxDynamicSharedMemorySize, GEMM_SMEM);
    cudaFuncSetAttribute(gemm_planes,
                         cudaFuncAttributeMaxDynamicSharedMemorySize, GEMM_SMEM);

    // side stream + events (created once; host-side resources only)
    static cudaStream_t s2 = nullptr;
    static cudaEvent_t evDeg = nullptr, evCSR = nullptr;
    if (!s2) {
        cudaStreamCreateWithFlags(&s2, cudaStreamNonBlocking);
        cudaEventCreateWithFlags(&evDeg, cudaEventDisableTiming);
        cudaEventCreateWithFlags(&evCSR, cudaEventDisableTiming);
    }

    // main stream: degrees (needed by both branches)
    zero_counters_kernel<<<(n + 255) / 256, 256>>>(n);
    count_deg_kernel<<<(e + 255) / 256, 256>>>(colp, e);
    cudaEventRecord(evDeg, 0);

    // stream B: CSR build (rowptr scan + fill) — overlaps with layer-0 GEMM
    cudaStreamWaitEvent(s2, evDeg, 0);
    scan1_kernel<<<nb, SCAN_B, 0, s2>>>(n);
    scan2_kernel<<<1, SCAN_B, 0, s2>>>(nb);
    scan3_kernel<<<nb, SCAN_B, 0, s2>>>(n, nb);
    fill_csr_kernel<<<(e + 255) / 256, 256, 0, s2>>>(rowp, colp, e);
    cudaEventRecord(evCSR, s2);

    // main stream: dinv + layer-0 GEMM (hides the CSR build)
    dinv_kernel<<<(n + 255) / 256, 256>>>(n);
    gemm_f32<<<gemmGrid, 1024, GEMM_SMEM>>>(x, W, n, numTiles);

    // join: aggregate needs CSR
    cudaStreamWaitEvent(0, evCSR, 0);
    aggregate_kernel<<<(n * 32 + 255) / 256, 256>>>(b, out, 1, n);  // layer 0

    for (int l = 1; l < LL; ++l) {
        gemm_planes<<<gemmGrid, 1024, GEMM_SMEM>>>(W + (size_t)l * DD * DD, n,
                                                   numTiles);
        aggregate_kernel<<<(n * 32 + 255) / 256, 256>>>(
            b + (size_t)l * DD, out, (l == LL - 1) ? 0 : 1, n);
    }
}